// round 14
// baseline (speedup 1.0000x reference)
#include <cuda_runtime.h>

// PowerLinear, single kernel: 16 producers (bid 0..15) + 256 GEMM consumers.
//   c = colsum(R), rs = rowsum(R)
//   n_b == 0 : y_b = (c . x_b) * rs     (sum of chunk-local cxp * rs over ks)
//   n_b >= 1 : y_b = R @ ( d^{n_b} * c * x_b )
// Producers: per-k-chunk colsum, rowsum partials, zero their out slice; exit.
// Consumers depend ONLY on producers => deadlock-free under any scheduling.
// Replay-safe: monotonic counters with epoch-derived targets; data buffers
// plainly overwritten (launches serialize on the stream).

#define DD 1024
#define KCHUNK 64
#define PADB 68           // float pad
#define PADW 66           // u64 pad
#define NPROD 16
#define NCONS 256
#define NBLK (NPROD + NCONS)   // 272

#define SWD_BYTES (KCHUNK * PADW * 8)       // 33792
#define SB_BYTES  (KCHUNK * PADB * 4)       // 17408
#define OFF_C     (SWD_BYTES + SB_BYTES)    // 51200
#define OFF_RS    (OFF_C + 256)
#define OFF_CXP   (OFF_RS + 256)
#define OFF_N0    (OFF_CXP + 256)
#define OFF_SCRED (OFF_N0 + 256)            // [4][64] floats
#define OFF_MISC  (OFF_SCRED + 1024)
#define SMEM_TOTAL (OFF_MISC + 64)          // 53376

typedef unsigned long long u64;

__device__ float    g_c[NPROD][64];      // final colsums per k-chunk
__device__ float    g_rsp[NPROD][DD];    // rowsum partials per producer
__device__ unsigned g_epoch;             // one bump per block per launch
__device__ unsigned g_ready[NPROD];      // producer publish counters

__device__ __forceinline__ void redadd2(float* p, float a, float b)
{
    asm volatile("red.global.add.v2.f32 [%0], {%1, %2};"
                 :: "l"(p), "f"(a), "f"(b) : "memory");
}
__device__ __forceinline__ void atom_add_release(unsigned* p, unsigned v)
{
    unsigned old;
    asm volatile("atom.release.gpu.global.add.u32 %0, [%1], %2;"
                 : "=r"(old) : "l"(p), "r"(v) : "memory");
}
__device__ __forceinline__ unsigned ldacq(const unsigned* p)
{
    unsigned v;
    asm volatile("ld.global.acquire.gpu.u32 %0, [%1];" : "=r"(v) : "l"(p));
    return v;
}
__device__ __forceinline__ void spin_until(const unsigned* p, unsigned target)
{
    for (;;) {
        unsigned c = ldacq(p);
        if ((int)(c - target) >= 0) break;
        __nanosleep(20);
    }
}
__device__ __forceinline__ u64 pk2(float lo, float hi)
{
    u64 r;
    asm("mov.b64 %0, {%1,%2};" : "=l"(r) : "f"(lo), "f"(hi));
    return r;
}
__device__ __forceinline__ void upk2(u64 v, float& lo, float& hi)
{
    asm("mov.b64 {%0,%1}, %2;" : "=f"(lo), "=f"(hi) : "l"(v));
}
__device__ __forceinline__ void fma2(u64& d, u64 a, u64 b)
{
    asm("fma.rn.f32x2 %0, %1, %2, %0;" : "+l"(d) : "l"(a), "l"(b));
}

__global__ __launch_bounds__(256, 2)
void fused_kernel(const float* __restrict__ x,
                  const int*   __restrict__ n,
                  const float* __restrict__ diag,
                  const float* __restrict__ R,
                  float*       __restrict__ out)
{
    extern __shared__ __align__(16) char smem_raw[];
    const int bid = blockIdx.x;
    const int tid = threadIdx.x;

    int* sm_m = (int*)(smem_raw + OFF_MISC);
    if (tid == 0) {
        unsigned e = atomicAdd(&g_epoch, 1u);
        sm_m[0] = (int)(e / NBLK);          // launch index (same for all blocks)
    }

    // ======================= PRODUCERS (bid 0..15) ==========================
    if (bid < NPROD) {
        const int pks = bid;                 // owns k-columns [64*pks, +64)
        float (*pr)[64] = (float (*)[64])smem_raw;   // [16][64] colsum partials

        const int q = tid & 15;              // 4-column quad within chunk
        const int g = tid >> 4;              // 64-row group
        const float* base = R + pks * KCHUNK + q * 4;

        float4 a = make_float4(0.f, 0.f, 0.f, 0.f);
#pragma unroll 8
        for (int r = 0; r < 64; r++) {
            const int row = g * 64 + r;
            float4 v = *(const float4*)(base + row * DD);
            a.x += v.x; a.y += v.y; a.z += v.z; a.w += v.w;
            // rowsum partial over this producer's 64 columns
            float rp = (v.x + v.y) + (v.z + v.w);
            rp += __shfl_down_sync(0xffffffffu, rp, 8, 16);
            rp += __shfl_down_sync(0xffffffffu, rp, 4, 16);
            rp += __shfl_down_sync(0xffffffffu, rp, 2, 16);
            rp += __shfl_down_sync(0xffffffffu, rp, 1, 16);
            if (q == 0) g_rsp[pks][row] = rp;
        }
        pr[g][q * 4 + 0] = a.x;
        pr[g][q * 4 + 1] = a.y;
        pr[g][q * 4 + 2] = a.z;
        pr[g][q * 4 + 3] = a.w;

        // zero this producer's slice of out (4096 floats)
        {
            float4 z = make_float4(0.f, 0.f, 0.f, 0.f);
            float* po = out + pks * 4096 + tid * 16;
            ((float4*)po)[0] = z; ((float4*)po)[1] = z;
            ((float4*)po)[2] = z; ((float4*)po)[3] = z;
        }

        __syncthreads();
        if (tid < 64) {
            float s = 0.f;
#pragma unroll
            for (int gg = 0; gg < 16; gg++) s += pr[gg][tid];
            g_c[pks][tid] = s;
        }
        __threadfence();
        __syncthreads();
        if (tid == 0) atom_add_release(&g_ready[pks], 1u);
        return;
    }

    // ======================= CONSUMERS (bid 16..271) ========================
    u64   (*sWd)[PADW] = (u64 (*)[PADW])(smem_raw);
    float (*sB)[PADB]  = (float (*)[PADB])(smem_raw + SWD_BYTES);
    float* sm_c   = (float*)(smem_raw + OFF_C);
    float* sm_rs  = (float*)(smem_raw + OFF_RS);
    float* sm_cxp = (float*)(smem_raw + OFF_CXP);
    int*   sm_n0  = (int*)(smem_raw + OFF_N0);
    float (*scred)[64] = (float (*)[64])(smem_raw + OFF_SCRED);

    const int cb = bid - NPROD;
    const int it = cb >> 4;
    const int ks = cb & 15;
    const int i0 = it * 64;
    const int k0 = ks * KCHUNK;

    // ---- load R tile -------------------------------------------------------
    const int li = tid >> 2;            // row in tile (i)
    const int lk = (tid & 3) * 4;       // k offset {0,4,8,12}
    const float* rptr = R + (i0 + li) * DD + k0 + lk;
    float4 ra0 = *(const float4*)(rptr);
    float4 ra1 = *(const float4*)(rptr + 16);
    float4 ra2 = *(const float4*)(rptr + 32);
    float4 ra3 = *(const float4*)(rptr + 48);

    // ---- prefetch x/diag for W build ---------------------------------------
    const int wb = tid >> 2;
    const int wq = (tid & 3) * 4;
    const int nb = n[wb];
    float4 xv[4], dv[4];
#pragma unroll
    for (int m = 0; m < 4; m++) {
        const int kk = wq + 16 * m;
        xv[m] = *(const float4*)(x + wb * DD + k0 + kk);
        dv[m] = *(const float4*)(diag + k0 + kk);
    }

    // store R tile transposed into sB
    {
        float4 rv[4] = {ra0, ra1, ra2, ra3};
#pragma unroll
        for (int s = 0; s < 4; s++) {
            const int kr = s * 16 + lk;
            sB[kr + 0][li] = rv[s].x;
            sB[kr + 1][li] = rv[s].y;
            sB[kr + 2][li] = rv[s].z;
            sB[kr + 3][li] = rv[s].w;
        }
    }
    __syncthreads();                       // sB + sm_m[0] published
    const int lidx = sm_m[0];

    // ---- wait only for OWN producer's c ------------------------------------
    if (tid == 0) spin_until(&g_ready[ks], (unsigned)(lidx + 1));
    __syncthreads();
    if (tid < 64) sm_c[tid] = g_c[ks][tid];
    __syncthreads();

    // ---- build duplicated W tile + chunk-local cxp -------------------------
    {
        float cxp = 0.f;
#pragma unroll
        for (int m = 0; m < 4; m++) {
            const int kk = wq + 16 * m;
            float xs[4] = {xv[m].x, xv[m].y, xv[m].z, xv[m].w};
            float ds[4] = {dv[m].x, dv[m].y, dv[m].z, dv[m].w};
#pragma unroll
            for (int c = 0; c < 4; c++) {
                const float cx = sm_c[kk + c] * xs[c];
                cxp += cx;
                float p = 1.f;
#pragma unroll
                for (int k = 0; k < 5; k++) p *= (k < nb) ? ds[c] : 1.f;
                const float w = (nb == 0) ? 0.f : cx * p;
                sWd[kk + c][wb] = pk2(w, w);
            }
        }
        cxp += __shfl_down_sync(0xffffffffu, cxp, 1, 4);
        cxp += __shfl_down_sync(0xffffffffu, cxp, 2, 4);
        if ((tid & 3) == 0) {
            sm_cxp[wb] = cxp;
            sm_n0[wb]  = (nb == 0);
        }
    }
    __syncthreads();

    // ---- main loop: 64 k iterations, 8 FFMA2 each --------------------------
    const int tx = tid & 15;            // i quad
    const int ty = tid >> 4;            // b quad
    const int i4 = tx * 4;
    const int b4 = ty * 4;

    u64 acc[4][2];
#pragma unroll
    for (int r = 0; r < 4; r++) { acc[r][0] = 0ull; acc[r][1] = 0ull; }

#pragma unroll 16
    for (int kk = 0; kk < KCHUNK; kk++) {
        ulonglong2 w01 = *(const ulonglong2*)&sWd[kk][b4];
        ulonglong2 w23 = *(const ulonglong2*)&sWd[kk][b4 + 2];
        ulonglong2 rr  = *(const ulonglong2*)&sB[kk][i4];
        fma2(acc[0][0], w01.x, rr.x); fma2(acc[0][1], w01.x, rr.y);
        fma2(acc[1][0], w01.y, rr.x); fma2(acc[1][1], w01.y, rr.y);
        fma2(acc[2][0], w23.x, rr.x); fma2(acc[2][1], w23.x, rr.y);
        fma2(acc[3][0], w23.y, rr.x); fma2(acc[3][1], w23.y, rr.y);
    }

    // ---- wait for ALL producers (free by now), gather rs -------------------
    if (tid < NPROD) spin_until(&g_ready[tid], (unsigned)(lidx + 1));
    __syncthreads();
    {
        const int i  = tid & 63;
        const int ph = tid >> 6;        // 4 producers each
        float s = 0.f;
#pragma unroll
        for (int p = ph * 4; p < ph * 4 + 4; p++)
            s += g_rsp[p][i0 + i];
        scred[ph][i] = s;
    }
    __syncthreads();
    if (tid < 64)
        sm_rs[tid] = (scred[0][tid] + scred[1][tid]) +
                     (scred[2][tid] + scred[3][tid]);
    __syncthreads();

    // ---- epilogue: vector atomics + n==0 rank-1 term -----------------------
    const float rs0 = sm_rs[i4 + 0];
    const float rs1 = sm_rs[i4 + 1];
    const float rs2 = sm_rs[i4 + 2];
    const float rs3 = sm_rs[i4 + 3];
#pragma unroll
    for (int r = 0; r < 4; r++) {
        const int b = b4 + r;
        const float ex = sm_n0[b] ? sm_cxp[b] : 0.f;
        float v0, v1, v2, v3;
        upk2(acc[r][0], v0, v1);
        upk2(acc[r][1], v2, v3);
        float* po = out + b * DD + i0 + i4;
        redadd2(po,     v0 + ex * rs0, v1 + ex * rs1);
        redadd2(po + 2, v2 + ex * rs2, v3 + ex * rs3);
    }
}

// ---------------------------------------------------------------------------
extern "C" void kernel_launch(void* const* d_in, const int* in_sizes, int n_in,
                              void* d_out, int out_size)
{
    const float* x    = (const float*)d_in[0];
    const int*   nn   = (const int*)  d_in[1];
    const float* diag = (const float*)d_in[2];
    const float* rot  = (const float*)d_in[3];
    float* out = (float*)d_out;

    cudaFuncSetAttribute(fused_kernel,
                         cudaFuncAttributeMaxDynamicSharedMemorySize,
                         SMEM_TOTAL);

    fused_kernel<<<NBLK, 256, SMEM_TOTAL>>>(x, nn, diag, rot, out);
}

// round 15
// speedup vs baseline: 1.1556x; 1.1556x over previous
#include <cuda_runtime.h>

// PowerLinear, single kernel: 16 colsum/cx producers (bid 0..15) + 256 GEMM
// consumers.
//   c = colsum(R); cx_b = c . x_b
//   W[b,j] = (n_b==0) ? cx_b : c_j * d_j^{n_b} * x[b,j]   (n0 rows constant!)
//   y[b,i] = sum_j W[b,j] * R[i,j]      (split-K atomics; n0 handled by W)
// Producers exit early; consumers depend only on producers (deadlock-free).
// Replay-safe: monotonic release counters + epoch-derived targets; data
// buffers plainly overwritten each launch.

#define DD 1024
#define KCHUNK 64
#define PADB 68
#define NPROD 16
#define NCONS 256
#define NBLK (NPROD + NCONS)   // 272

__device__ float    g_c[NPROD][64];     // final colsum per k-chunk
__device__ float    g_cxp[NPROD][64];   // cx partials per k-chunk
__device__ unsigned g_epoch;
__device__ unsigned g_ready[NPROD];

__device__ __forceinline__ void redadd2(float* p, float a, float b)
{
    asm volatile("red.global.add.v2.f32 [%0], {%1, %2};"
                 :: "l"(p), "f"(a), "f"(b) : "memory");
}
__device__ __forceinline__ void atom_add_release(unsigned* p, unsigned v)
{
    unsigned old;
    asm volatile("atom.release.gpu.global.add.u32 %0, [%1], %2;"
                 : "=r"(old) : "l"(p), "r"(v) : "memory");
}
__device__ __forceinline__ unsigned ldacq(const unsigned* p)
{
    unsigned v;
    asm volatile("ld.global.acquire.gpu.u32 %0, [%1];" : "=r"(v) : "l"(p));
    return v;
}
__device__ __forceinline__ void spin_until(const unsigned* p, unsigned target)
{
    for (;;) {
        unsigned c = ldacq(p);
        if ((int)(c - target) >= 0) break;
        __nanosleep(20);
    }
}

__global__ __launch_bounds__(256, 2)
void fused_kernel(const float* __restrict__ x,
                  const int*   __restrict__ n,
                  const float* __restrict__ diag,
                  const float* __restrict__ R,
                  float*       __restrict__ out)
{
    __shared__ __align__(16) float sW[KCHUNK][PADB];   // W[k][b]
    __shared__ __align__(16) float sB[KCHUNK][PADB];   // R[k][i] transposed
    __shared__ float sm_c[64];
    __shared__ float sm_cx[64];
    __shared__ int   sm_m[16];

    const int bid = blockIdx.x;
    const int tid = threadIdx.x;

    if (tid == 0) {
        unsigned e = atomicAdd(&g_epoch, 1u);
        sm_m[0] = (int)(e / NBLK);          // launch index
    }

    // ======================= PRODUCERS (bid 0..15) ==========================
    if (bid < NPROD) {
        const int p = bid;                  // owns k-columns [64p, 64p+64)
        float (*pr)[64] = (float (*)[64])sW;   // reuse sW as [16][64]

        const int q = tid & 15;             // 4-col quad
        const int g = tid >> 4;             // 64-row group
        const float* base = R + p * KCHUNK + q * 4;
        float4 a = make_float4(0.f, 0.f, 0.f, 0.f);
#pragma unroll 8
        for (int r = 0; r < 64; r++) {
            float4 v = *(const float4*)(base + (g * 64 + r) * DD);
            a.x += v.x; a.y += v.y; a.z += v.z; a.w += v.w;
        }
        pr[g][q * 4 + 0] = a.x;
        pr[g][q * 4 + 1] = a.y;
        pr[g][q * 4 + 2] = a.z;
        pr[g][q * 4 + 3] = a.w;

        // zero this producer's slice of out (4096 floats)
        {
            float4 z = make_float4(0.f, 0.f, 0.f, 0.f);
            float* po = out + p * 4096 + tid * 16;
            ((float4*)po)[0] = z; ((float4*)po)[1] = z;
            ((float4*)po)[2] = z; ((float4*)po)[3] = z;
        }

        __syncthreads();
        if (tid < 64) {
            float s = 0.f;
#pragma unroll
            for (int gg = 0; gg < 16; gg++) s += pr[gg][tid];
            sm_c[tid]  = s;
            g_c[p][tid] = s;
        }
        __syncthreads();

        // cx partial: b = tid (64 threads), dot c-chunk with x[b, chunk]
        if (tid < 64) {
            const float* xb = x + tid * DD + p * KCHUNK;
            float cx = 0.f;
#pragma unroll
            for (int m = 0; m < 16; m++) {
                float4 xv = *(const float4*)(xb + m * 4);
                float4 cv = *(const float4*)&sm_c[m * 4];
                cx += cv.x * xv.x + cv.y * xv.y + cv.z * xv.z + cv.w * xv.w;
            }
            g_cxp[p][tid] = cx;
        }
        __threadfence();
        __syncthreads();
        if (tid == 0) atom_add_release(&g_ready[p], 1u);
        return;
    }

    // ======================= CONSUMERS (bid 16..271) ========================
    const int cb = bid - NPROD;
    const int it = cb >> 4;
    const int ks = cb & 15;
    const int i0 = it * 64;
    const int k0 = ks * KCHUNK;

    // ---- load R tile -------------------------------------------------------
    const int li = tid >> 2;            // row in tile (i)
    const int lk = (tid & 3) * 4;       // k offset {0,4,8,12}
    const float* rptr = R + (i0 + li) * DD + k0 + lk;
    float4 ra0 = *(const float4*)(rptr);
    float4 ra1 = *(const float4*)(rptr + 16);
    float4 ra2 = *(const float4*)(rptr + 32);
    float4 ra3 = *(const float4*)(rptr + 48);

    // ---- prefetch x/diag for W build ---------------------------------------
    const int wb = tid >> 2;            // b row this thread builds
    const int wq = (tid & 3) * 4;       // k quad base
    const int nb = n[wb];
    float4 xv[4], dv[4];
#pragma unroll
    for (int m = 0; m < 4; m++) {
        const int kk = wq + 16 * m;
        xv[m] = *(const float4*)(x + wb * DD + k0 + kk);
        dv[m] = *(const float4*)(diag + k0 + kk);
    }

    // store R tile transposed into sB
    {
        float4 rv[4] = {ra0, ra1, ra2, ra3};
#pragma unroll
        for (int s = 0; s < 4; s++) {
            const int kr = s * 16 + lk;
            sB[kr + 0][li] = rv[s].x;
            sB[kr + 1][li] = rv[s].y;
            sB[kr + 2][li] = rv[s].z;
            sB[kr + 3][li] = rv[s].w;
        }
    }
    __syncthreads();                     // sB + sm_m[0] published
    const int lidx = sm_m[0];

    // ---- wait for all producers (they run concurrently with our prologue) --
    if (tid < NPROD) spin_until(&g_ready[tid], (unsigned)(lidx + 1));
    __syncthreads();

    // ---- read c chunk + global cx ------------------------------------------
    if (tid < 64) {
        sm_c[tid] = g_c[ks][tid];
    } else if (tid < 128) {
        const int b = tid - 64;
        float s = 0.f;
#pragma unroll
        for (int p = 0; p < NPROD; p++) s += g_cxp[p][b];
        sm_cx[b] = s;
    }
    __syncthreads();

    // ---- build W tile (n0 rows = cx_b constant) ----------------------------
    {
        const float cxb = sm_cx[wb];
#pragma unroll
        for (int m = 0; m < 4; m++) {
            const int kk = wq + 16 * m;
            float xs[4] = {xv[m].x, xv[m].y, xv[m].z, xv[m].w};
            float ds[4] = {dv[m].x, dv[m].y, dv[m].z, dv[m].w};
#pragma unroll
            for (int c = 0; c < 4; c++) {
                float p = 1.f;
#pragma unroll
                for (int k = 0; k < 5; k++) p *= (k < nb) ? ds[c] : 1.f;
                sW[kk + c][wb] = (nb == 0) ? cxb : sm_c[kk + c] * xs[c] * p;
            }
        }
    }
    __syncthreads();

    // ---- main loop: 64 k iterations, 16 scalar FMAs each -------------------
    const int tx = tid & 15;
    const int ty = tid >> 4;
    const int i4 = tx * 4;
    const int b4 = ty * 4;

    float acc[4][4];
#pragma unroll
    for (int r = 0; r < 4; r++)
#pragma unroll
        for (int c = 0; c < 4; c++) acc[r][c] = 0.f;

#pragma unroll 16
    for (int kk = 0; kk < KCHUNK; kk++) {
        const float4 av = *(const float4*)&sW[kk][b4];
        const float4 bv = *(const float4*)&sB[kk][i4];
        acc[0][0] = fmaf(av.x, bv.x, acc[0][0]);
        acc[0][1] = fmaf(av.x, bv.y, acc[0][1]);
        acc[0][2] = fmaf(av.x, bv.z, acc[0][2]);
        acc[0][3] = fmaf(av.x, bv.w, acc[0][3]);
        acc[1][0] = fmaf(av.y, bv.x, acc[1][0]);
        acc[1][1] = fmaf(av.y, bv.y, acc[1][1]);
        acc[1][2] = fmaf(av.y, bv.z, acc[1][2]);
        acc[1][3] = fmaf(av.y, bv.w, acc[1][3]);
        acc[2][0] = fmaf(av.z, bv.x, acc[2][0]);
        acc[2][1] = fmaf(av.z, bv.y, acc[2][1]);
        acc[2][2] = fmaf(av.z, bv.z, acc[2][2]);
        acc[2][3] = fmaf(av.z, bv.w, acc[2][3]);
        acc[3][0] = fmaf(av.w, bv.x, acc[3][0]);
        acc[3][1] = fmaf(av.w, bv.y, acc[3][1]);
        acc[3][2] = fmaf(av.w, bv.z, acc[3][2]);
        acc[3][3] = fmaf(av.w, bv.w, acc[3][3]);
    }

    // ---- epilogue: pure vector atomics -------------------------------------
#pragma unroll
    for (int r = 0; r < 4; r++) {
        float* po = out + (b4 + r) * DD + i0 + i4;
        redadd2(po,     acc[r][0], acc[r][1]);
        redadd2(po + 2, acc[r][2], acc[r][3]);
    }
}

// ---------------------------------------------------------------------------
extern "C" void kernel_launch(void* const* d_in, const int* in_sizes, int n_in,
                              void* d_out, int out_size)
{
    const float* x    = (const float*)d_in[0];
    const int*   nn   = (const int*)  d_in[1];
    const float* diag = (const float*)d_in[2];
    const float* rot  = (const float*)d_in[3];
    float* out = (float*)d_out;

    fused_kernel<<<NBLK, 256>>>(x, nn, diag, rot, out);
}